// round 1
// baseline (speedup 1.0000x reference)
#include <cuda_runtime.h>

#define N_NODES 50000
#define N_EDGES 1600000
#define HD 32
#define DIN_N 128
#define FULL 0xffffffffu

// ---------------- device scratch (static, allocation-free) ----------------
__device__ float g_Hn1[N_NODES * HD];
__device__ float g_Hn2[N_NODES * HD];
__device__ float g_Pns[N_NODES * HD];
__device__ float g_Pnd[N_NODES * HD];
__device__ float g_num1[N_NODES * HD];
__device__ float g_den1[N_NODES * 4];
__device__ float g_num2[N_NODES * HD];
__device__ float g_den2[N_NODES * 4];
__device__ float g_G1[51200000];           // E * 32  (Ef @ Wc1 + c1)
__device__ float g_Wc1[HD * HD];
__device__ float g_c1[HD];

// ---------------- helpers ----------------
__device__ __forceinline__ float f4c(const float4 v, int c) {
    switch (c & 3) {
        case 0: return v.x;
        case 1: return v.y;
        case 2: return v.z;
        default: return v.w;
    }
}

__device__ __forceinline__ void red_add_v4(float* addr, float4 v) {
    asm volatile("red.global.add.v4.f32 [%0], {%1,%2,%3,%4};"
                 :: "l"(addr), "f"(v.x), "f"(v.y), "f"(v.z), "f"(v.w)
                 : "memory");
}

// ---------------- zero accumulators (must run every launch: graph replay) --
__global__ void k_zero() {
    int t = blockIdx.x * blockDim.x + threadIdx.x;
    if (t < N_NODES * HD) { g_num1[t] = 0.f; g_num2[t] = 0.f; }
    if (t < N_NODES * 4)  { g_den1[t] = 0.f; g_den2[t] = 0.f; }
}

// ---------------- weight folding: Wc1 = We1 @ Weo1[64:96], c1 = beo1 + be1@Weo1[64:96]
__global__ void k_fold(const float* __restrict__ We1, const float* __restrict__ Weo1,
                       const float* __restrict__ be1, const float* __restrict__ beo1) {
    int t = threadIdx.x;           // 1024 threads
    int i = t >> 5, j = t & 31;
    float acc = 0.f;
#pragma unroll
    for (int k = 0; k < 32; k++) acc += We1[i * 32 + k] * Weo1[(64 + k) * 32 + j];
    g_Wc1[i * 32 + j] = acc;
    if (i == 0) {
        float c = beo1[j];
#pragma unroll
        for (int k = 0; k < 32; k++) c += be1[k] * Weo1[(64 + k) * 32 + j];
        g_c1[j] = c;
    }
}

// ---------------- Hn1 = NF @ Wn1 + bn1   (8 lanes/node, 4 nodes/warp) ------
__global__ void k_hn1(const float* __restrict__ NF, const float* __restrict__ Wn1,
                      const float* __restrict__ bn1) {
    __shared__ __align__(16) float sW[DIN_N * HD];     // 16 KB
    for (int t = threadIdx.x; t < DIN_N * HD; t += blockDim.x) sW[t] = Wn1[t];
    __syncthreads();
    int lane = threadIdx.x & 31, warp = threadIdx.x >> 5;
    int node = blockIdx.x * 32 + warp * 4 + (lane >> 3);
    int nodec = node < N_NODES ? node : N_NODES - 1;
    int l = lane & 7;
    const float4* nfr = (const float4*)(NF + (size_t)nodec * DIN_N);
    float4 nf0 = nfr[l * 4 + 0], nf1 = nfr[l * 4 + 1], nf2 = nfr[l * 4 + 2], nf3 = nfr[l * 4 + 3];
    float4 acc = *(const float4*)(bn1 + 4 * l);
    const float4* sW4 = (const float4*)sW;
#pragma unroll
    for (int i = 0; i < DIN_N; i++) {
        int p = i & 15;
        float x = (p < 4) ? f4c(nf0, p) : (p < 8) ? f4c(nf1, p) : (p < 12) ? f4c(nf2, p) : f4c(nf3, p);
        float v = __shfl_sync(FULL, x, i >> 4, 8);
        float4 w = sW4[i * 8 + l];
        acc.x += v * w.x; acc.y += v * w.y; acc.z += v * w.z; acc.w += v * w.w;
    }
    if (node < N_NODES) *(float4*)(g_Hn1 + node * HD + 4 * l) = acc;
}

// ---------------- Pns = Hn1 @ Weo1[0:32], Pnd = Hn1 @ Weo1[32:64] ----------
__global__ void k_pn(const float* __restrict__ Weo1) {
    __shared__ __align__(16) float sWs[HD * HD];
    __shared__ __align__(16) float sWd[HD * HD];
    for (int t = threadIdx.x; t < HD * HD; t += blockDim.x) {
        sWs[t] = Weo1[t]; sWd[t] = Weo1[HD * HD + t];
    }
    __syncthreads();
    int lane = threadIdx.x & 31, warp = threadIdx.x >> 5;
    int node = blockIdx.x * 32 + warp * 4 + (lane >> 3);
    int nodec = node < N_NODES ? node : N_NODES - 1;
    int l = lane & 7;
    float4 h = *(const float4*)(g_Hn1 + nodec * HD + 4 * l);
    float4 as_ = make_float4(0.f, 0.f, 0.f, 0.f), ad_ = make_float4(0.f, 0.f, 0.f, 0.f);
    const float4* s4 = (const float4*)sWs;
    const float4* d4 = (const float4*)sWd;
#pragma unroll
    for (int i = 0; i < HD; i++) {
        float v = __shfl_sync(FULL, f4c(h, i & 3), i >> 2, 8);
        float4 ws = s4[i * 8 + l], wd = d4[i * 8 + l];
        as_.x += v * ws.x; as_.y += v * ws.y; as_.z += v * ws.z; as_.w += v * ws.w;
        ad_.x += v * wd.x; ad_.y += v * wd.y; ad_.z += v * wd.z; ad_.w += v * wd.w;
    }
    if (node < N_NODES) {
        *(float4*)(g_Pns + node * HD + 4 * l) = as_;
        *(float4*)(g_Pnd + node * HD + 4 * l) = ad_;
    }
}

// ---------------- Edge pass, layer 1 ---------------------------------------
// he = Ef@We1+be1 ; G1 = Ef@Wc1+c1 (stored) ; logits, ex=exp(lrelu) ;
// num1[dst] += ex*(hs+he), den1[dst,h] += ex
__global__ void k_e1(const float* __restrict__ EF, const int* __restrict__ idx,
                     const float* __restrict__ We1, const float* __restrict__ be1,
                     const float* __restrict__ as1, const float* __restrict__ ad1,
                     const float* __restrict__ ae1) {
    __shared__ __align__(16) float sWe[HD * HD];
    __shared__ __align__(16) float sWc[HD * HD];
    __shared__ __align__(16) float sAs[HD], sAd[HD], sAe[HD], sBe[HD], sC1[HD];
    int t0 = threadIdx.x;
    for (int t = t0; t < HD * HD; t += blockDim.x) { sWe[t] = We1[t]; sWc[t] = g_Wc1[t]; }
    if (t0 < HD) {
        sAs[t0] = as1[t0]; sAd[t0] = ad1[t0]; sAe[t0] = ae1[t0];
        sBe[t0] = be1[t0]; sC1[t0] = g_c1[t0];
    }
    __syncthreads();
    int lane = t0 & 31, warp = t0 >> 5;
    int edge = blockIdx.x * 32 + warp * 4 + (lane >> 3);   // grid exact: E/32 blocks
    int l = lane & 7;
    float4 ef = *(const float4*)(EF + (size_t)edge * HD + 4 * l);
    float4 he = *(const float4*)(sBe + 4 * l);
    float4 g  = *(const float4*)(sC1 + 4 * l);
    const float4* w4 = (const float4*)sWe;
    const float4* c4 = (const float4*)sWc;
#pragma unroll
    for (int i = 0; i < HD; i++) {
        float v = __shfl_sync(FULL, f4c(ef, i & 3), i >> 2, 8);
        float4 a = w4[i * 8 + l], b = c4[i * 8 + l];
        he.x += v * a.x; he.y += v * a.y; he.z += v * a.z; he.w += v * a.w;
        g.x  += v * b.x; g.y  += v * b.y; g.z  += v * b.z; g.w  += v * b.w;
    }
    *(float4*)(g_G1 + (size_t)edge * HD + 4 * l) = g;
    int src = __ldg(idx + edge);
    int dst = __ldg(idx + N_EDGES + edge);
    float4 hs = *(const float4*)(g_Hn1 + (size_t)src * HD + 4 * l);
    float4 hd = *(const float4*)(g_Hn1 + (size_t)dst * HD + 4 * l);
    float p = hs.x * sAs[4 * l]     + hs.y * sAs[4 * l + 1] + hs.z * sAs[4 * l + 2] + hs.w * sAs[4 * l + 3]
            + hd.x * sAd[4 * l]     + hd.y * sAd[4 * l + 1] + hd.z * sAd[4 * l + 2] + hd.w * sAd[4 * l + 3]
            + he.x * sAe[4 * l]     + he.y * sAe[4 * l + 1] + he.z * sAe[4 * l + 2] + he.w * sAe[4 * l + 3];
    p += __shfl_xor_sync(FULL, p, 1);                 // sum the two lanes of this head
    float logit = p > 0.f ? p : 0.2f * p;             // leaky_relu(0.2)
    float ex = __expf(logit);                         // no max-shift (see analysis)
    float4 m;
    m.x = ex * (hs.x + he.x); m.y = ex * (hs.y + he.y);
    m.z = ex * (hs.z + he.z); m.w = ex * (hs.w + he.w);
    red_add_v4(g_num1 + (size_t)dst * HD + 4 * l, m);
    if ((lane & 1) == 0) atomicAdd(g_den1 + dst * 4 + (l >> 1), ex);
}

// ---------------- x1 = softmax(num1/(den1+1e-9)); Hn2 = x1 @ Wn2 + bn2 -----
__global__ void k_x1hn2(const float* __restrict__ Wn2, const float* __restrict__ bn2) {
    __shared__ __align__(16) float sW[HD * HD];
    for (int t = threadIdx.x; t < HD * HD; t += blockDim.x) sW[t] = Wn2[t];
    __syncthreads();
    int lane = threadIdx.x & 31, warp = threadIdx.x >> 5;
    int node = blockIdx.x * 32 + warp * 4 + (lane >> 3);
    int nodec = node < N_NODES ? node : N_NODES - 1;
    int l = lane & 7;
    float4 nm = *(const float4*)(g_num1 + nodec * HD + 4 * l);
    float den = g_den1[nodec * 4 + (l >> 1)];
    float inv = 1.f / (den + 1e-9f);
    float4 v = make_float4(nm.x * inv, nm.y * inv, nm.z * inv, nm.w * inv);
    // softmax over 32 dims (in-lane 4 + butterfly over 8 lanes)
    float mx = fmaxf(fmaxf(v.x, v.y), fmaxf(v.z, v.w));
    mx = fmaxf(mx, __shfl_xor_sync(FULL, mx, 1));
    mx = fmaxf(mx, __shfl_xor_sync(FULL, mx, 2));
    mx = fmaxf(mx, __shfl_xor_sync(FULL, mx, 4));
    float4 e = make_float4(__expf(v.x - mx), __expf(v.y - mx), __expf(v.z - mx), __expf(v.w - mx));
    float s = e.x + e.y + e.z + e.w;
    s += __shfl_xor_sync(FULL, s, 1);
    s += __shfl_xor_sync(FULL, s, 2);
    s += __shfl_xor_sync(FULL, s, 4);
    float is = 1.f / s;
    float4 y = make_float4(e.x * is, e.y * is, e.z * is, e.w * is);
    float4 acc = *(const float4*)(bn2 + 4 * l);
    const float4* sW4 = (const float4*)sW;
#pragma unroll
    for (int i = 0; i < HD; i++) {
        float b = __shfl_sync(FULL, f4c(y, i & 3), i >> 2, 8);
        float4 w = sW4[i * 8 + l];
        acc.x += b * w.x; acc.y += b * w.y; acc.z += b * w.z; acc.w += b * w.w;
    }
    if (node < N_NODES) *(float4*)(g_Hn2 + node * HD + 4 * l) = acc;
}

// ---------------- Edge pass, layer 2 ---------------------------------------
// y = softmax(Pns[src]+Pnd[dst]+G1) ; he2 = y@We2+be2 ; logits2, ex2 ;
// num2[dst] += ex2*(hs2+he2), den2 += ex2.  (layer-2 edge output y2 is unused)
__global__ void k_e2(const int* __restrict__ idx,
                     const float* __restrict__ We2, const float* __restrict__ be2,
                     const float* __restrict__ as2, const float* __restrict__ ad2,
                     const float* __restrict__ ae2) {
    __shared__ __align__(16) float sWe[HD * HD];
    __shared__ __align__(16) float sAs[HD], sAd[HD], sAe[HD], sBe[HD];
    int t0 = threadIdx.x;
    for (int t = t0; t < HD * HD; t += blockDim.x) sWe[t] = We2[t];
    if (t0 < HD) { sAs[t0] = as2[t0]; sAd[t0] = ad2[t0]; sAe[t0] = ae2[t0]; sBe[t0] = be2[t0]; }
    __syncthreads();
    int lane = t0 & 31, warp = t0 >> 5;
    int edge = blockIdx.x * 32 + warp * 4 + (lane >> 3);
    int l = lane & 7;
    float4 g = *(const float4*)(g_G1 + (size_t)edge * HD + 4 * l);
    int src = __ldg(idx + edge);
    int dst = __ldg(idx + N_EDGES + edge);
    float4 ps = *(const float4*)(g_Pns + (size_t)src * HD + 4 * l);
    float4 pd = *(const float4*)(g_Pnd + (size_t)dst * HD + 4 * l);
    float4 v = make_float4(g.x + ps.x + pd.x, g.y + ps.y + pd.y,
                           g.z + ps.z + pd.z, g.w + ps.w + pd.w);
    float mx = fmaxf(fmaxf(v.x, v.y), fmaxf(v.z, v.w));
    mx = fmaxf(mx, __shfl_xor_sync(FULL, mx, 1));
    mx = fmaxf(mx, __shfl_xor_sync(FULL, mx, 2));
    mx = fmaxf(mx, __shfl_xor_sync(FULL, mx, 4));
    float4 e = make_float4(__expf(v.x - mx), __expf(v.y - mx), __expf(v.z - mx), __expf(v.w - mx));
    float s = e.x + e.y + e.z + e.w;
    s += __shfl_xor_sync(FULL, s, 1);
    s += __shfl_xor_sync(FULL, s, 2);
    s += __shfl_xor_sync(FULL, s, 4);
    float is = 1.f / s;
    float4 y = make_float4(e.x * is, e.y * is, e.z * is, e.w * is);
    float4 he = *(const float4*)(sBe + 4 * l);
    const float4* w4 = (const float4*)sWe;
#pragma unroll
    for (int i = 0; i < HD; i++) {
        float b = __shfl_sync(FULL, f4c(y, i & 3), i >> 2, 8);
        float4 w = w4[i * 8 + l];
        he.x += b * w.x; he.y += b * w.y; he.z += b * w.z; he.w += b * w.w;
    }
    float4 hs = *(const float4*)(g_Hn2 + (size_t)src * HD + 4 * l);
    float4 hd = *(const float4*)(g_Hn2 + (size_t)dst * HD + 4 * l);
    float p = hs.x * sAs[4 * l]     + hs.y * sAs[4 * l + 1] + hs.z * sAs[4 * l + 2] + hs.w * sAs[4 * l + 3]
            + hd.x * sAd[4 * l]     + hd.y * sAd[4 * l + 1] + hd.z * sAd[4 * l + 2] + hd.w * sAd[4 * l + 3]
            + he.x * sAe[4 * l]     + he.y * sAe[4 * l + 1] + he.z * sAe[4 * l + 2] + he.w * sAe[4 * l + 3];
    p += __shfl_xor_sync(FULL, p, 1);
    float logit = p > 0.f ? p : 0.2f * p;
    float ex = __expf(logit);
    float4 m;
    m.x = ex * (hs.x + he.x); m.y = ex * (hs.y + he.y);
    m.z = ex * (hs.z + he.z); m.w = ex * (hs.w + he.w);
    red_add_v4(g_num2 + (size_t)dst * HD + 4 * l, m);
    if ((lane & 1) == 0) atomicAdd(g_den2 + dst * 4 + (l >> 1), ex);
}

// ---------------- x2 = relu(num2/(den2+1e-9)); out = x2 @ Wl + bl ----------
__global__ void k_out(const float* __restrict__ Wl, const float* __restrict__ bl,
                      float* __restrict__ out) {
    int lane = threadIdx.x & 31, warp = threadIdx.x >> 5;
    int node = blockIdx.x * 32 + warp * 4 + (lane >> 3);
    int nodec = node < N_NODES ? node : N_NODES - 1;
    int l = lane & 7;
    float4 nm = *(const float4*)(g_num2 + nodec * HD + 4 * l);
    float den = g_den2[nodec * 4 + (l >> 1)];
    float inv = 1.f / (den + 1e-9f);
    float4 x = make_float4(fmaxf(nm.x * inv, 0.f), fmaxf(nm.y * inv, 0.f),
                           fmaxf(nm.z * inv, 0.f), fmaxf(nm.w * inv, 0.f));
    float4 w = *(const float4*)(Wl + 4 * l);
    float a = x.x * w.x + x.y * w.y + x.z * w.z + x.w * w.w;
    a += __shfl_xor_sync(FULL, a, 1);
    a += __shfl_xor_sync(FULL, a, 2);
    a += __shfl_xor_sync(FULL, a, 4);
    if (node < N_NODES && l == 0) out[node] = a + __ldg(bl);
}

// ---------------- launch ----------------------------------------------------
extern "C" void kernel_launch(void* const* d_in, const int* in_sizes, int n_in,
                              void* d_out, int out_size) {
    const float* NF   = (const float*)d_in[0];
    const float* EF   = (const float*)d_in[1];
    const int*   IDX  = (const int*)d_in[2];      // int32 (jax default randint)
    const float* Wn1  = (const float*)d_in[3];
    const float* bn1  = (const float*)d_in[4];
    const float* We1  = (const float*)d_in[5];
    const float* be1  = (const float*)d_in[6];
    const float* as1  = (const float*)d_in[7];
    const float* ad1  = (const float*)d_in[8];
    const float* ae1  = (const float*)d_in[9];
    const float* Weo1 = (const float*)d_in[10];
    const float* beo1 = (const float*)d_in[11];
    const float* Wn2  = (const float*)d_in[12];
    const float* bn2  = (const float*)d_in[13];
    const float* We2  = (const float*)d_in[14];
    const float* be2  = (const float*)d_in[15];
    const float* as2  = (const float*)d_in[16];
    const float* ad2  = (const float*)d_in[17];
    const float* ae2  = (const float*)d_in[18];
    // d_in[19] = Weo2, d_in[20] = beo2 : provably unused by the output
    const float* Wl   = (const float*)d_in[21];
    const float* bl   = (const float*)d_in[22];
    float* out = (float*)d_out;

    int nodeBlocks = (N_NODES + 31) / 32;         // 32 nodes per 256-thread block
    int edgeBlocks = N_EDGES / 32;                // exact: 50000

    k_zero<<<(N_NODES * HD + 255) / 256, 256>>>();
    k_fold<<<1, 1024>>>(We1, Weo1, be1, beo1);
    k_hn1<<<nodeBlocks, 256>>>(NF, Wn1, bn1);
    k_pn<<<nodeBlocks, 256>>>(Weo1);
    k_e1<<<edgeBlocks, 256>>>(EF, IDX, We1, be1, as1, ad1, ae1);
    k_x1hn2<<<nodeBlocks, 256>>>(Wn2, bn2);
    k_e2<<<edgeBlocks, 256>>>(IDX, We2, be2, as2, ad2, ae2);
    k_out<<<nodeBlocks, 256>>>(Wl, bl, out);
}

// round 2
// speedup vs baseline: 1.7067x; 1.7067x over previous
#include <cuda_runtime.h>

#define N_NODES 50000
#define N_EDGES 1600000
#define HD 32
#define DIN_N 128
#define FULL 0xffffffffu

typedef unsigned long long ull;

// ---------------- device scratch (static, allocation-free) ----------------
__device__ __align__(16) float g_Hn1[N_NODES * HD];
__device__ __align__(16) float g_Hn2[N_NODES * HD];
__device__ __align__(16) float g_Pns[N_NODES * HD];
__device__ __align__(16) float g_Pnd[N_NODES * HD];
__device__ __align__(16) float g_num1[N_NODES * HD];
__device__ __align__(16) float g_den1[N_NODES * 4];
__device__ __align__(16) float g_num2[N_NODES * HD];
__device__ __align__(16) float g_den2[N_NODES * 4];
__device__ __align__(16) float g_G1[51200000];           // E * 32  (Ef @ Wc1 + c1)
__device__ __align__(16) float g_Wc1[HD * HD];
__device__ __align__(16) float g_c1[HD];

// ---------------- helpers ----------------
__device__ __forceinline__ float f4c(const float4 v, int c) {
    switch (c & 3) {
        case 0: return v.x;
        case 1: return v.y;
        case 2: return v.z;
        default: return v.w;
    }
}
__device__ __forceinline__ int i4c(const int4 v, int c) {
    switch (c & 3) {
        case 0: return v.x;
        case 1: return v.y;
        case 2: return v.z;
        default: return v.w;
    }
}

// packed fp32x2 FMA (Blackwell): full fp32 precision, 2x FMA-pipe throughput
__device__ __forceinline__ ull splat2(float v) {
    ull r; asm("mov.b64 %0, {%1, %1};" : "=l"(r) : "f"(v)); return r;
}
__device__ __forceinline__ ull pack2(float a, float b) {
    ull r; asm("mov.b64 %0, {%1, %2};" : "=l"(r) : "f"(a), "f"(b)); return r;
}
__device__ __forceinline__ ull fma2(ull a, ull b, ull c) {
    ull d; asm("fma.rn.f32x2 %0, %1, %2, %3;" : "=l"(d) : "l"(a), "l"(b), "l"(c)); return d;
}
__device__ __forceinline__ float2 unpack2(ull p) {
    float2 f; asm("mov.b64 {%0, %1}, %2;" : "=f"(f.x), "=f"(f.y) : "l"(p)); return f;
}

__device__ __forceinline__ void red_add_v4(float* addr, float4 v) {
    asm volatile("red.global.add.v4.f32 [%0], {%1,%2,%3,%4};"
                 :: "l"(addr), "f"(v.x), "f"(v.y), "f"(v.z), "f"(v.w)
                 : "memory");
}

// ---------------- zero accumulators (must run every launch: graph replay) --
__global__ void k_zero() {
    int t = blockIdx.x * blockDim.x + threadIdx.x;
    if (t < N_NODES * HD) { g_num1[t] = 0.f; g_num2[t] = 0.f; }
    if (t < N_NODES * 4)  { g_den1[t] = 0.f; g_den2[t] = 0.f; }
}

// ---------------- weight folding: Wc1 = We1 @ Weo1[64:96], c1 = beo1 + be1@Weo1[64:96]
__global__ void k_fold(const float* __restrict__ We1, const float* __restrict__ Weo1,
                       const float* __restrict__ be1, const float* __restrict__ beo1) {
    int t = threadIdx.x;           // 1024 threads
    int i = t >> 5, j = t & 31;
    float acc = 0.f;
#pragma unroll
    for (int k = 0; k < 32; k++) acc += We1[i * 32 + k] * Weo1[(64 + k) * 32 + j];
    g_Wc1[i * 32 + j] = acc;
    if (i == 0) {
        float c = beo1[j];
#pragma unroll
        for (int k = 0; k < 32; k++) c += be1[k] * Weo1[(64 + k) * 32 + j];
        g_c1[j] = c;
    }
}

// ---------------- Hn1 = NF @ Wn1 + bn1   (8 lanes/node, 4 nodes/warp) ------
__global__ void k_hn1(const float* __restrict__ NF, const float* __restrict__ Wn1,
                      const float* __restrict__ bn1) {
    __shared__ __align__(16) float sW[DIN_N * HD];     // 16 KB
    for (int t = threadIdx.x; t < DIN_N * HD; t += blockDim.x) sW[t] = Wn1[t];
    __syncthreads();
    int lane = threadIdx.x & 31, warp = threadIdx.x >> 5;
    int node = blockIdx.x * 32 + warp * 4 + (lane >> 3);
    int nodec = node < N_NODES ? node : N_NODES - 1;
    int l = lane & 7;
    const float4* nfr = (const float4*)(NF + (size_t)nodec * DIN_N);
    float4 nf0 = nfr[l * 4 + 0], nf1 = nfr[l * 4 + 1], nf2 = nfr[l * 4 + 2], nf3 = nfr[l * 4 + 3];
    float4 acc = *(const float4*)(bn1 + 4 * l);
    const float4* sW4 = (const float4*)sW;
#pragma unroll
    for (int i = 0; i < DIN_N; i++) {
        int p = i & 15;
        float x = (p < 4) ? f4c(nf0, p) : (p < 8) ? f4c(nf1, p) : (p < 12) ? f4c(nf2, p) : f4c(nf3, p);
        float v = __shfl_sync(FULL, x, i >> 4, 8);
        float4 w = sW4[i * 8 + l];
        acc.x += v * w.x; acc.y += v * w.y; acc.z += v * w.z; acc.w += v * w.w;
    }
    if (node < N_NODES) *(float4*)(g_Hn1 + node * HD + 4 * l) = acc;
}

// ---------------- Pns = Hn1 @ Weo1[0:32], Pnd = Hn1 @ Weo1[32:64] ----------
__global__ void k_pn(const float* __restrict__ Weo1) {
    __shared__ __align__(16) float sWs[HD * HD];
    __shared__ __align__(16) float sWd[HD * HD];
    for (int t = threadIdx.x; t < HD * HD; t += blockDim.x) {
        sWs[t] = Weo1[t]; sWd[t] = Weo1[HD * HD + t];
    }
    __syncthreads();
    int lane = threadIdx.x & 31, warp = threadIdx.x >> 5;
    int node = blockIdx.x * 32 + warp * 4 + (lane >> 3);
    int nodec = node < N_NODES ? node : N_NODES - 1;
    int l = lane & 7;
    float4 h = *(const float4*)(g_Hn1 + nodec * HD + 4 * l);
    float4 as_ = make_float4(0.f, 0.f, 0.f, 0.f), ad_ = make_float4(0.f, 0.f, 0.f, 0.f);
    const float4* s4 = (const float4*)sWs;
    const float4* d4 = (const float4*)sWd;
#pragma unroll
    for (int i = 0; i < HD; i++) {
        float v = __shfl_sync(FULL, f4c(h, i & 3), i >> 2, 8);
        float4 ws = s4[i * 8 + l], wd = d4[i * 8 + l];
        as_.x += v * ws.x; as_.y += v * ws.y; as_.z += v * ws.z; as_.w += v * ws.w;
        ad_.x += v * wd.x; ad_.y += v * wd.y; ad_.z += v * wd.z; ad_.w += v * wd.w;
    }
    if (node < N_NODES) {
        *(float4*)(g_Pns + node * HD + 4 * l) = as_;
        *(float4*)(g_Pnd + node * HD + 4 * l) = ad_;
    }
}

// ---------------- Edge pass, layer 1 (4 edges per 8-lane group) ------------
// he = Ef@We1+be1 ; G1 = Ef@Wc1+c1 (stored) ; logits, ex=exp(lrelu) ;
// num1[dst] += ex*(hs+he), den1[dst,h] += ex
__global__ void __launch_bounds__(256)
k_e1(const float* __restrict__ EF, const int* __restrict__ idx,
     const float* __restrict__ We1, const float* __restrict__ be1,
     const float* __restrict__ as1, const float* __restrict__ ad1,
     const float* __restrict__ ae1) {
    int lane = threadIdx.x & 31, warp = threadIdx.x >> 5;
    int g = lane >> 3, l = lane & 7;
    int e0 = (blockIdx.x * 8 + warp) * 16 + g * 4;

    float4 As = *(const float4*)(as1 + 4 * l);
    float4 Ad = *(const float4*)(ad1 + 4 * l);
    float4 Ae = *(const float4*)(ae1 + 4 * l);
    float4 be = *(const float4*)(be1 + 4 * l);
    float4 c1 = *(const float4*)(g_c1 + 4 * l);

    // streaming loads of 4 edge-feature rows (evict-first: keep W in L1)
    float4 ef[4];
#pragma unroll
    for (int t = 0; t < 4; t++)
        ef[t] = __ldcs((const float4*)(EF + (size_t)(e0 + t) * HD + 4 * l));

    ull acc_he[4][2], acc_g[4][2];
#pragma unroll
    for (int t = 0; t < 4; t++) {
        acc_he[t][0] = pack2(be.x, be.y); acc_he[t][1] = pack2(be.z, be.w);
        acc_g[t][0]  = pack2(c1.x, c1.y); acc_g[t][1]  = pack2(c1.z, c1.w);
    }

    const ulonglong2* W2 = (const ulonglong2*)We1;    // row i, cols 4l..4l+3
    const ulonglong2* C2 = (const ulonglong2*)g_Wc1;
#pragma unroll
    for (int i = 0; i < HD; i++) {
        ulonglong2 w = __ldg(W2 + i * 8 + l);
        ulonglong2 c = __ldg(C2 + i * 8 + l);
#pragma unroll
        for (int t = 0; t < 4; t++) {
            float v = __shfl_sync(FULL, f4c(ef[t], i & 3), i >> 2, 8);
            ull vv = splat2(v);
            acc_he[t][0] = fma2(w.x, vv, acc_he[t][0]);
            acc_he[t][1] = fma2(w.y, vv, acc_he[t][1]);
            acc_g[t][0]  = fma2(c.x, vv, acc_g[t][0]);
            acc_g[t][1]  = fma2(c.y, vv, acc_g[t][1]);
        }
    }

    int4 srcs = *(const int4*)(idx + e0);
    int4 dsts = *(const int4*)(idx + N_EDGES + e0);

#pragma unroll
    for (int t = 0; t < 4; t++) {
        int src = i4c(srcs, t), dst = i4c(dsts, t);
        float2 g0 = unpack2(acc_g[t][0]), g1 = unpack2(acc_g[t][1]);
        __stcs((float4*)(g_G1 + (size_t)(e0 + t) * HD + 4 * l),
               make_float4(g0.x, g0.y, g1.x, g1.y));
        float2 h0 = unpack2(acc_he[t][0]), h1 = unpack2(acc_he[t][1]);
        float4 hs = *(const float4*)(g_Hn1 + (size_t)src * HD + 4 * l);
        float4 hd = *(const float4*)(g_Hn1 + (size_t)dst * HD + 4 * l);
        float p = hs.x * As.x + hs.y * As.y + hs.z * As.z + hs.w * As.w
                + hd.x * Ad.x + hd.y * Ad.y + hd.z * Ad.z + hd.w * Ad.w
                + h0.x * Ae.x + h0.y * Ae.y + h1.x * Ae.z + h1.y * Ae.w;
        p += __shfl_xor_sync(FULL, p, 1);
        float logit = p > 0.f ? p : 0.2f * p;
        float ex = __expf(logit);
        float4 m = make_float4(ex * (hs.x + h0.x), ex * (hs.y + h0.y),
                               ex * (hs.z + h1.x), ex * (hs.w + h1.y));
        red_add_v4(g_num1 + (size_t)dst * HD + 4 * l, m);
        if ((l & 1) == 0) atomicAdd(g_den1 + dst * 4 + (l >> 1), ex);
    }
}

// ---------------- x1 = softmax(num1/(den1+1e-9)); Hn2 = x1 @ Wn2 + bn2 -----
__global__ void k_x1hn2(const float* __restrict__ Wn2, const float* __restrict__ bn2) {
    __shared__ __align__(16) float sW[HD * HD];
    for (int t = threadIdx.x; t < HD * HD; t += blockDim.x) sW[t] = Wn2[t];
    __syncthreads();
    int lane = threadIdx.x & 31, warp = threadIdx.x >> 5;
    int node = blockIdx.x * 32 + warp * 4 + (lane >> 3);
    int nodec = node < N_NODES ? node : N_NODES - 1;
    int l = lane & 7;
    float4 nm = *(const float4*)(g_num1 + nodec * HD + 4 * l);
    float den = g_den1[nodec * 4 + (l >> 1)];
    float inv = 1.f / (den + 1e-9f);
    float4 v = make_float4(nm.x * inv, nm.y * inv, nm.z * inv, nm.w * inv);
    float mx = fmaxf(fmaxf(v.x, v.y), fmaxf(v.z, v.w));
    mx = fmaxf(mx, __shfl_xor_sync(FULL, mx, 1));
    mx = fmaxf(mx, __shfl_xor_sync(FULL, mx, 2));
    mx = fmaxf(mx, __shfl_xor_sync(FULL, mx, 4));
    float4 e = make_float4(__expf(v.x - mx), __expf(v.y - mx), __expf(v.z - mx), __expf(v.w - mx));
    float s = e.x + e.y + e.z + e.w;
    s += __shfl_xor_sync(FULL, s, 1);
    s += __shfl_xor_sync(FULL, s, 2);
    s += __shfl_xor_sync(FULL, s, 4);
    float is = 1.f / s;
    float4 y = make_float4(e.x * is, e.y * is, e.z * is, e.w * is);
    float4 acc = *(const float4*)(bn2 + 4 * l);
    const float4* sW4 = (const float4*)sW;
#pragma unroll
    for (int i = 0; i < HD; i++) {
        float b = __shfl_sync(FULL, f4c(y, i & 3), i >> 2, 8);
        float4 w = sW4[i * 8 + l];
        acc.x += b * w.x; acc.y += b * w.y; acc.z += b * w.z; acc.w += b * w.w;
    }
    if (node < N_NODES) *(float4*)(g_Hn2 + node * HD + 4 * l) = acc;
}

// ---------------- Edge pass, layer 2 (4 edges per 8-lane group) ------------
// y = softmax(Pns[src]+Pnd[dst]+G1) ; he2 = y@We2+be2 ; logits2, ex2 ;
// num2[dst] += ex2*(hs2+he2), den2 += ex2.  (layer-2 edge output is unused)
__global__ void __launch_bounds__(256)
k_e2(const int* __restrict__ idx,
     const float* __restrict__ We2, const float* __restrict__ be2,
     const float* __restrict__ as2, const float* __restrict__ ad2,
     const float* __restrict__ ae2) {
    int lane = threadIdx.x & 31, warp = threadIdx.x >> 5;
    int g = lane >> 3, l = lane & 7;
    int e0 = (blockIdx.x * 8 + warp) * 16 + g * 4;

    float4 As = *(const float4*)(as2 + 4 * l);
    float4 Ad = *(const float4*)(ad2 + 4 * l);
    float4 Ae = *(const float4*)(ae2 + 4 * l);
    float4 be = *(const float4*)(be2 + 4 * l);

    int4 srcs = *(const int4*)(idx + e0);
    int4 dsts = *(const int4*)(idx + N_EDGES + e0);

    // reconstruct y = softmax(G1 + Pns[src] + Pnd[dst]) for 4 edges
    float4 y[4];
#pragma unroll
    for (int t = 0; t < 4; t++) {
        int src = i4c(srcs, t), dst = i4c(dsts, t);
        float4 gg = __ldcs((const float4*)(g_G1 + (size_t)(e0 + t) * HD + 4 * l));
        float4 ps = *(const float4*)(g_Pns + (size_t)src * HD + 4 * l);
        float4 pd = *(const float4*)(g_Pnd + (size_t)dst * HD + 4 * l);
        float4 v = make_float4(gg.x + ps.x + pd.x, gg.y + ps.y + pd.y,
                               gg.z + ps.z + pd.z, gg.w + ps.w + pd.w);
        float mx = fmaxf(fmaxf(v.x, v.y), fmaxf(v.z, v.w));
        mx = fmaxf(mx, __shfl_xor_sync(FULL, mx, 1));
        mx = fmaxf(mx, __shfl_xor_sync(FULL, mx, 2));
        mx = fmaxf(mx, __shfl_xor_sync(FULL, mx, 4));
        float4 e = make_float4(__expf(v.x - mx), __expf(v.y - mx),
                               __expf(v.z - mx), __expf(v.w - mx));
        float s = e.x + e.y + e.z + e.w;
        s += __shfl_xor_sync(FULL, s, 1);
        s += __shfl_xor_sync(FULL, s, 2);
        s += __shfl_xor_sync(FULL, s, 4);
        float is = 1.f / s;
        y[t] = make_float4(e.x * is, e.y * is, e.z * is, e.w * is);
    }

    ull acc[4][2];
#pragma unroll
    for (int t = 0; t < 4; t++) { acc[t][0] = pack2(be.x, be.y); acc[t][1] = pack2(be.z, be.w); }

    const ulonglong2* W2 = (const ulonglong2*)We2;
#pragma unroll
    for (int i = 0; i < HD; i++) {
        ulonglong2 w = __ldg(W2 + i * 8 + l);
#pragma unroll
        for (int t = 0; t < 4; t++) {
            float v = __shfl_sync(FULL, f4c(y[t], i & 3), i >> 2, 8);
            ull vv = splat2(v);
            acc[t][0] = fma2(w.x, vv, acc[t][0]);
            acc[t][1] = fma2(w.y, vv, acc[t][1]);
        }
    }

#pragma unroll
    for (int t = 0; t < 4; t++) {
        int src = i4c(srcs, t), dst = i4c(dsts, t);
        float2 h0 = unpack2(acc[t][0]), h1 = unpack2(acc[t][1]);
        float4 hs = *(const float4*)(g_Hn2 + (size_t)src * HD + 4 * l);
        float4 hd = *(const float4*)(g_Hn2 + (size_t)dst * HD + 4 * l);
        float p = hs.x * As.x + hs.y * As.y + hs.z * As.z + hs.w * As.w
                + hd.x * Ad.x + hd.y * Ad.y + hd.z * Ad.z + hd.w * Ad.w
                + h0.x * Ae.x + h0.y * Ae.y + h1.x * Ae.z + h1.y * Ae.w;
        p += __shfl_xor_sync(FULL, p, 1);
        float logit = p > 0.f ? p : 0.2f * p;
        float ex = __expf(logit);
        float4 m = make_float4(ex * (hs.x + h0.x), ex * (hs.y + h0.y),
                               ex * (hs.z + h1.x), ex * (hs.w + h1.y));
        red_add_v4(g_num2 + (size_t)dst * HD + 4 * l, m);
        if ((l & 1) == 0) atomicAdd(g_den2 + dst * 4 + (l >> 1), ex);
    }
}

// ---------------- x2 = relu(num2/(den2+1e-9)); out = x2 @ Wl + bl ----------
__global__ void k_out(const float* __restrict__ Wl, const float* __restrict__ bl,
                      float* __restrict__ out) {
    int lane = threadIdx.x & 31, warp = threadIdx.x >> 5;
    int node = blockIdx.x * 32 + warp * 4 + (lane >> 3);
    int nodec = node < N_NODES ? node : N_NODES - 1;
    int l = lane & 7;
    float4 nm = *(const float4*)(g_num2 + nodec * HD + 4 * l);
    float den = g_den2[nodec * 4 + (l >> 1)];
    float inv = 1.f / (den + 1e-9f);
    float4 x = make_float4(fmaxf(nm.x * inv, 0.f), fmaxf(nm.y * inv, 0.f),
                           fmaxf(nm.z * inv, 0.f), fmaxf(nm.w * inv, 0.f));
    float4 w = *(const float4*)(Wl + 4 * l);
    float a = x.x * w.x + x.y * w.y + x.z * w.z + x.w * w.w;
    a += __shfl_xor_sync(FULL, a, 1);
    a += __shfl_xor_sync(FULL, a, 2);
    a += __shfl_xor_sync(FULL, a, 4);
    if (node < N_NODES && l == 0) out[node] = a + __ldg(bl);
}

// ---------------- launch ----------------------------------------------------
extern "C" void kernel_launch(void* const* d_in, const int* in_sizes, int n_in,
                              void* d_out, int out_size) {
    const float* NF   = (const float*)d_in[0];
    const float* EF   = (const float*)d_in[1];
    const int*   IDX  = (const int*)d_in[2];
    const float* Wn1  = (const float*)d_in[3];
    const float* bn1  = (const float*)d_in[4];
    const float* We1  = (const float*)d_in[5];
    const float* be1  = (const float*)d_in[6];
    const float* as1  = (const float*)d_in[7];
    const float* ad1  = (const float*)d_in[8];
    const float* ae1  = (const float*)d_in[9];
    const float* Weo1 = (const float*)d_in[10];
    const float* beo1 = (const float*)d_in[11];
    const float* Wn2  = (const float*)d_in[12];
    const float* bn2  = (const float*)d_in[13];
    const float* We2  = (const float*)d_in[14];
    const float* be2  = (const float*)d_in[15];
    const float* as2  = (const float*)d_in[16];
    const float* ad2  = (const float*)d_in[17];
    const float* ae2  = (const float*)d_in[18];
    // d_in[19] = Weo2, d_in[20] = beo2 : unused by the output
    const float* Wl   = (const float*)d_in[21];
    const float* bl   = (const float*)d_in[22];
    float* out = (float*)d_out;

    int nodeBlocks = (N_NODES + 31) / 32;
    int edgeBlocks = N_EDGES / 128;               // 16 edges/warp * 8 warps = 128/block

    k_zero<<<(N_NODES * HD + 255) / 256, 256>>>();
    k_fold<<<1, 1024>>>(We1, Weo1, be1, beo1);
    k_hn1<<<nodeBlocks, 256>>>(NF, Wn1, bn1);
    k_pn<<<nodeBlocks, 256>>>(Weo1);
    k_e1<<<edgeBlocks, 256>>>(EF, IDX, We1, be1, as1, ad1, ae1);
    k_x1hn2<<<nodeBlocks, 256>>>(Wn2, bn2);
    k_e2<<<edgeBlocks, 256>>>(IDX, We2, be2, as2, ad2, ae2);
    k_out<<<nodeBlocks, 256>>>(Wl, bl, out);
}